// round 11
// baseline (speedup 1.0000x reference)
#include <cuda_runtime.h>
#include <cuda_bf16.h>
#include <cstdint>

// Problem constants
#define T_ 2048
#define B_ 64
#define D_ 256
#define H_ 256
#define L_ 2
#define M_ (T_ * B_)       // 131072 GEMM rows per layer

// Quantization constants.  W ~ U(-s, s), s = 1/sqrt(512) exactly (from reference).
// A ≈ sA*(128*Ah + Al), W ≈ sW*(128*Wh + Wl); sW = s/16256; layer-1 sA = 1/16256.
#define WINV    ((float)(16256.0 * 22.627416997969522))   // 16256/s
#define FSW     ((float)(0.044194173824159216 / 127.0))   // sW*128 = s/127
#define F_L1    ((float)(0.044194173824159216 / 127.0 / 16256.0))

// W image: per (l, ntile 0..15): blocks [hl][kb] (hl: 0=hi 1=lo; kb: K 0..127 / 128..255),
// each block 64 n-rows x 128 k int8 = 8KB, rows 128B, unit swz ((j^(row&7))<<4).
__device__ __align__(16) unsigned char g_W[(size_t)L_ * 16 * 4 * 8192];   // 1 MB
// A image: per m-tile (128 rows): [Ah kb0 | Ah kb1 | Al kb0 | Al kb1], 4 x 16KB = 64KB.
__device__ __align__(16) unsigned char g_A[(size_t)(M_ / 128) * 65536];   // 67 MB
__device__ float g_Ascale[M_];                                            // per-row sA (layer 0)
__device__ __align__(16) float4 g_bias4[(size_t)L_ * B_ * H_];            // [l][b][h].(f,i,g,o)

// ---------------------------------------------------------------------------
// helpers
// ---------------------------------------------------------------------------
__device__ __forceinline__ uint32_t smem_u32(const void* p)
{
    uint32_t a;
    asm("{ .reg .u64 t; cvta.to.shared.u64 t, %1; cvt.u32.u64 %0, t; }" : "=r"(a) : "l"(p));
    return a;
}
__device__ __forceinline__ float sigmoidf_(float x)
{
    return __fdividef(1.0f, 1.0f + __expf(-x));
}
__device__ __forceinline__ float tanhf_(float x)
{
    return 1.0f - __fdividef(2.0f, 1.0f + __expf(2.0f * x));
}
__device__ __forceinline__ uint32_t pack4_s8(float a, float b, float c, float d)
{
    int v0 = __float2int_rn(a) & 0xFF;
    int v1 = __float2int_rn(b) & 0xFF;
    int v2 = __float2int_rn(c) & 0xFF;
    int v3 = __float2int_rn(d) & 0xFF;
    return (uint32_t)(v0 | (v1 << 8) | (v2 << 16) | (v3 << 24));
}

#define CP16(s, g) asm volatile("cp.async.cg.shared.global [%0], [%1], 16;" :: "r"(s), "l"(g))
#define CP_COMMIT() asm volatile("cp.async.commit_group;" ::: "memory")
#define CP_WAIT2() asm volatile("cp.async.wait_group 2;" ::: "memory")
#define CP_WAIT0() asm volatile("cp.async.wait_group 0;" ::: "memory")

#define LDSM4(r, addr) asm volatile( \
    "ldmatrix.sync.aligned.m8n8.x4.shared.b16 {%0,%1,%2,%3}, [%4];" \
    : "=r"((r)[0]), "=r"((r)[1]), "=r"((r)[2]), "=r"((r)[3]) : "r"(addr))

#define MMA_S8(d, a, b0, b1) asm volatile( \
    "mma.sync.aligned.m16n8k32.row.col.s32.s8.s8.s32 " \
    "{%0,%1,%2,%3},{%4,%5,%6,%7},{%8,%9},{%0,%1,%2,%3};" \
    : "+r"((d)[0]), "+r"((d)[1]), "+r"((d)[2]), "+r"((d)[3]) \
    : "r"((a)[0]), "r"((a)[1]), "r"((a)[2]), "r"((a)[3]), "r"(b0), "r"(b1))

// ---------------------------------------------------------------------------
// Kernel 1: W -> int8 hi/lo image. Thread = one 16B unit (16 k of one n-col).
//   EXACTLY 65536 threads (256 blocks x 256): j:3 | nloc:6 | kb:1 | hl:1 | nt:4 | l:1
// ---------------------------------------------------------------------------
__global__ void __launch_bounds__(256) wprep_kernel(const float* __restrict__ W)
{
    int idx = blockIdx.x * 256 + threadIdx.x;      // 65536
    int j = idx & 7;
    int nloc = (idx >> 3) & 63;
    int kb = (idx >> 9) & 1;
    int hl = (idx >> 10) & 1;
    int nt = (idx >> 11) & 15;
    int l = (idx >> 15) & 1;

    int n = nt * 64 + nloc, g = n & 3, h = n >> 2;
    int k0 = kb * 128 + j * 16;
    const float* wp = W + ((size_t)(l * 4 + g) * 512 + k0) * 256 + h;

    uint32_t u[4];
#pragma unroll
    for (int p = 0; p < 4; p++) {
        float v[4];
#pragma unroll
        for (int i = 0; i < 4; i++) {
            float q = wp[(size_t)(p * 4 + i) * 256] * WINV;
            float qh = rintf(q * 0.0078125f);
            v[i] = hl ? rintf(q - 128.0f * qh) : qh;
        }
        u[p] = pack4_s8(v[0], v[1], v[2], v[3]);
    }
    unsigned off = (unsigned)nloc * 128 + (((unsigned)j ^ ((unsigned)nloc & 7)) << 4);
    size_t blk = ((size_t)(l * 16 + nt) * 2 + hl) * 2 + kb;
    *(uint4*)(g_W + blk * 8192 + off) = make_uint4(u[0], u[1], u[2], u[3]);
}

// ---------------------------------------------------------------------------
// Kernel 2: A(fp32) -> int8 hi/lo image with per-row scale (layer 0 inputs).
//   One warp per row: lane owns 8 k; warp-max -> sA; quantize; write 8B hi/lo.
// ---------------------------------------------------------------------------
__global__ void __launch_bounds__(256) aprep_kernel(const float* __restrict__ A, int t_stride)
{
    int lane = threadIdx.x & 31;
    int m = blockIdx.x * 8 + (threadIdx.x >> 5);

    const float* gp = A + (size_t)(m >> 6) * t_stride + (size_t)(m & 63) * 256 + lane * 8;
    float4 va = *(const float4*)gp;
    float4 vb = *(const float4*)(gp + 4);
    float v[8] = { va.x, va.y, va.z, va.w, vb.x, vb.y, vb.z, vb.w };

    float amax = 0.0f;
#pragma unroll
    for (int i = 0; i < 8; i++) amax = fmaxf(amax, fabsf(v[i]));
#pragma unroll
    for (int s = 16; s >= 1; s >>= 1)
        amax = fmaxf(amax, __shfl_xor_sync(0xffffffffu, amax, s));
    float rmax = fmaxf(amax, 1e-20f);
    float inv = 16256.0f / rmax;

    float hq[8], lq[8];
#pragma unroll
    for (int i = 0; i < 8; i++) {
        float q = v[i] * inv;
        hq[i] = rintf(q * 0.0078125f);
        lq[i] = rintf(q - 128.0f * hq[i]);
    }
    uint2 hi = make_uint2(pack4_s8(hq[0], hq[1], hq[2], hq[3]),
                          pack4_s8(hq[4], hq[5], hq[6], hq[7]));
    uint2 lo = make_uint2(pack4_s8(lq[0], lq[1], lq[2], lq[3]),
                          pack4_s8(lq[4], lq[5], lq[6], lq[7]));

    int mt = m >> 7, mloc = m & 127;
    int kb = lane >> 4, j = (lane >> 1) & 7;
    size_t base = (size_t)mt * 65536 + (size_t)kb * 16384 + (size_t)mloc * 128 +
                  (((unsigned)j ^ ((unsigned)mloc & 7)) << 4) + (unsigned)(lane & 1) * 8;
    *(uint2*)(g_A + base) = hi;
    *(uint2*)(g_A + base + 32768) = lo;
    if (lane == 0) g_Ascale[m] = rmax / 16256.0f;
}

// ---------------------------------------------------------------------------
// Kernel 3: effective bias (exact fp32): b[l,g,h] + sum_j h0[l,b,j]*W[l,g,D+j,h]
// ---------------------------------------------------------------------------
__global__ void __launch_bounds__(256) bias_kernel(const float* __restrict__ h0,
                                                   const float* __restrict__ W,
                                                   const float* __restrict__ bb)
{
    int idx = blockIdx.x * 256 + threadIdx.x;      // 131072
    int g = idx & 3;
    int h = (idx >> 2) & 255;
    int b = (idx >> 10) & 63;
    int l = (idx >> 16) & 1;

    const float* h0p = h0 + (l * B_ + b) * H_;
    const float* wp  = W + ((size_t)(l * 4 + g) * 512 + 256) * 256 + h;
    float acc = bb[(l * 4 + g) * H_ + h];
#pragma unroll 8
    for (int j = 0; j < H_; j++)
        acc = fmaf(h0p[j], wp[(size_t)j * 256], acc);
    ((float*)g_bias4)[idx] = acc;
}

// ---------------------------------------------------------------------------
// Kernel 4: int8 IMMA GEMM + fused LSTM epilogue.
//   CTA 128m x 64n, 256 thr = 8 warps (4m x 2n), warp tile 32x32.
//   acc1 = Ah*Wh; acc2 = Al*Wh + Ah*Wl; pre = F * (128*acc1 + acc2), F per-row.
//   Chunks (kb,hl): c0=(0,h) c1=(0,l) c2=(1,h) c3=(1,l), 4 bufs all prefilled.
//   Chunk = [A 16KB | W 8KB] = 24KB; grid: x = nt 0..15 (16 h), y = mt 0..1023.
// ---------------------------------------------------------------------------
#define CHUNK_BYTES 24576u
#define SMEM_SZ 98304

__global__ void __launch_bounds__(256, 2)
gemm_kernel(const float* __restrict__ c0, int l,
            float* __restrict__ hn, float* __restrict__ cn,
            float* __restrict__ x_out, int write_a, int use_rowscale)
{
    extern __shared__ __align__(1024) unsigned char smem[];
    const int tid = threadIdx.x;
    const int nt = blockIdx.x;
    const int mt = blockIdx.y;
    const int m0 = mt * 128;
    const uint32_t su = smem_u32(smem);
    const int lane = tid & 31, wid = tid >> 5;
    const int wm = wid >> 1, wn = wid & 1;

    const unsigned char* gWb = g_W + (size_t)(l * 16 + nt) * 32768;
    const unsigned char* gAb = g_A + (size_t)mt * 65536;

#define ISSUE_CHUNK(c, buf)                                                     \
    do {                                                                        \
        int hl_ = (c) & 1, kb_ = (c) >> 1;                                      \
        const unsigned char* sa = gAb + hl_ * 32768 + kb_ * 16384 + tid * 16;   \
        const unsigned char* sb = gWb + (size_t)(hl_ * 2 + kb_) * 8192 + tid * 16; \
        uint32_t da = su + (buf) * CHUNK_BYTES + tid * 16;                      \
        uint32_t db = da + 16384u;                                              \
        CP16(da, sa); CP16(da + 4096, sa + 4096);                               \
        CP16(da + 8192, sa + 8192); CP16(da + 12288, sa + 12288);               \
        CP16(db, sb); CP16(db + 4096, sb + 4096);                               \
        CP_COMMIT();                                                            \
    } while (0)

    // prefill all 4 chunks
    ISSUE_CHUNK(0, 0);
    ISSUE_CHUNK(1, 1);
    ISSUE_CHUNK(2, 2);
    ISSUE_CHUNK(3, 3);

    // per-lane ldmatrix offsets (byte-identical layout to the bf16 k16 path:
    // s8 k32 fragments == b16 k16 fragments reinterpreted as 2 x s8 along k)
    uint32_t aoff[2], aswz[2], boff[2], bswz[2];
    const uint32_t ua = (uint32_t)(lane >> 4);
    const uint32_t ub = (uint32_t)((lane >> 3) & 1);
#pragma unroll
    for (int tm = 0; tm < 2; tm++) {
        uint32_t row = (uint32_t)(wm * 32 + tm * 16 + (lane & 15));
        aoff[tm] = row * 128u;
        aswz[tm] = row & 7u;
    }
#pragma unroll
    for (int tn = 0; tn < 2; tn++) {
        uint32_t row = (uint32_t)(wn * 32 + tn * 16 + (lane & 7) + ((lane >> 4) << 3));
        boff[tn] = row * 128u + 16384u;
        bswz[tn] = row & 7u;
    }

    int acc1[2][4][4], acc2[2][4][4];
#pragma unroll
    for (int i = 0; i < 2; i++)
#pragma unroll
        for (int j = 0; j < 4; j++)
#pragma unroll
            for (int q = 0; q < 4; q++) { acc1[i][j][q] = 0; acc2[i][j][q] = 0; }

    // two kb-groups: group g uses bufs (2g) = (Ah|Wh), (2g+1) = (Al|Wl)
#pragma unroll 1
    for (int g = 0; g < 2; g++) {
        if (g == 0) { CP_WAIT2(); } else { CP_WAIT0(); }
        __syncthreads();
        const uint32_t be = su + (uint32_t)(2 * g) * CHUNK_BYTES;
        const uint32_t bo = be + CHUNK_BYTES;

#pragma unroll
        for (int ks = 0; ks < 4; ks++) {
            uint32_t ah[2][4], al[2][4], w[2][4];
            const uint32_t ka = (uint32_t)(ks * 2) + ua;
            const uint32_t kbv = (uint32_t)(ks * 2) + ub;

            // acc1 += Ah * Wh
#pragma unroll
            for (int tm = 0; tm < 2; tm++)
                LDSM4(ah[tm], be + aoff[tm] + ((ka ^ aswz[tm]) << 4));
#pragma unroll
            for (int tn = 0; tn < 2; tn++)
                LDSM4(w[tn], be + boff[tn] + ((kbv ^ bswz[tn]) << 4));
#pragma unroll
            for (int tm = 0; tm < 2; tm++)
#pragma unroll
                for (int tn = 0; tn < 2; tn++) {
                    MMA_S8(acc1[tm][tn * 2 + 0], ah[tm], w[tn][0], w[tn][1]);
                    MMA_S8(acc1[tm][tn * 2 + 1], ah[tm], w[tn][2], w[tn][3]);
                }

            // acc2 += Al * Wh (Wh in regs)
#pragma unroll
            for (int tm = 0; tm < 2; tm++)
                LDSM4(al[tm], bo + aoff[tm] + ((ka ^ aswz[tm]) << 4));
#pragma unroll
            for (int tm = 0; tm < 2; tm++)
#pragma unroll
                for (int tn = 0; tn < 2; tn++) {
                    MMA_S8(acc2[tm][tn * 2 + 0], al[tm], w[tn][0], w[tn][1]);
                    MMA_S8(acc2[tm][tn * 2 + 1], al[tm], w[tn][2], w[tn][3]);
                }

            // acc2 += Ah * Wl (Ah in regs; Wl overwrites Wh regs)
#pragma unroll
            for (int tn = 0; tn < 2; tn++)
                LDSM4(w[tn], bo + boff[tn] + ((kbv ^ bswz[tn]) << 4));
#pragma unroll
            for (int tm = 0; tm < 2; tm++)
#pragma unroll
                for (int tn = 0; tn < 2; tn++) {
                    MMA_S8(acc2[tm][tn * 2 + 0], ah[tm], w[tn][0], w[tn][1]);
                    MMA_S8(acc2[tm][tn * 2 + 1], ah[tm], w[tn][2], w[tn][3]);
                }
        }
        __syncthreads();
    }

    // stage combined value (128*acc1 + acc2, exact in int32) as fp32; pad 68
    {
        float* stage = (float*)smem;
        const int r0 = lane >> 2, cp2 = (lane & 3) * 2;
#pragma unroll
        for (int tm = 0; tm < 2; tm++) {
            int mr = wm * 32 + tm * 16 + r0;
#pragma unroll
            for (int j = 0; j < 4; j++) {
                int nc = wn * 32 + j * 8 + cp2;
                stage[(size_t)mr * 68 + nc] =
                    (float)(acc1[tm][j][0] * 128 + acc2[tm][j][0]);
                stage[(size_t)mr * 68 + nc + 1] =
                    (float)(acc1[tm][j][1] * 128 + acc2[tm][j][1]);
                stage[(size_t)(mr + 8) * 68 + nc] =
                    (float)(acc1[tm][j][2] * 128 + acc2[tm][j][2]);
                stage[(size_t)(mr + 8) * 68 + nc + 1] =
                    (float)(acc1[tm][j][3] * 128 + acc2[tm][j][3]);
            }
        }
    }
    __syncthreads();

    // fused LSTM epilogue: 256 items = 128 rows x 2 half-rows (8 h each)
    {
        const float* stage = (const float*)smem;
        int hu = tid & 1, mloc = tid >> 1;
        int m = m0 + mloc;
        int t = m >> 6, b = m & 63;
        int hbase = nt * 16 + hu * 8;

        float F = use_rowscale ? g_Ascale[m] * FSW : F_L1;
        const float4* bp = g_bias4 + (size_t)(l * B_ + b) * H_ + hbase;
        const float* c0p = c0 + ((size_t)l * B_ + b) * H_ + hbase;
        float hv[8], cc[8];
#pragma unroll
        for (int q = 0; q < 8; q++) {
            float4 pre = *(const float4*)&stage[(size_t)mloc * 68 + (hu * 8 + q) * 4];
            float4 bv = bp[q];
            float f  = sigmoidf_(fmaf(F, pre.x, bv.x));
            float ii = sigmoidf_(fmaf(F, pre.y, bv.y));
            float gt = tanhf_(fmaf(F, pre.z, bv.z));
            float o  = sigmoidf_(fmaf(F, pre.w, bv.w));
            cc[q] = fmaf(f, c0p[q], ii * gt);
            hv[q] = o * tanhf_(cc[q]);
        }
        size_t ob = (size_t)t * (L_ * B_ * H_) + (size_t)l * (B_ * H_) +
                    (size_t)b * H_ + hbase;
        *(float4*)&hn[ob]     = make_float4(hv[0], hv[1], hv[2], hv[3]);
        *(float4*)&hn[ob + 4] = make_float4(hv[4], hv[5], hv[6], hv[7]);
        *(float4*)&cn[ob]     = make_float4(cc[0], cc[1], cc[2], cc[3]);
        *(float4*)&cn[ob + 4] = make_float4(cc[4], cc[5], cc[6], cc[7]);

        if (write_a) {
            // emit int8 hi/lo A-image (fixed scale 1/16256, |h|<1) for layer 1
            float hq[8], lq[8];
#pragma unroll
            for (int q = 0; q < 8; q++) {
                float qq = hv[q] * 16256.0f;
                hq[q] = rintf(qq * 0.0078125f);
                lq[q] = rintf(qq - 128.0f * hq[q]);
            }
            uint2 hi = make_uint2(pack4_s8(hq[0], hq[1], hq[2], hq[3]),
                                  pack4_s8(hq[4], hq[5], hq[6], hq[7]));
            uint2 lo = make_uint2(pack4_s8(lq[0], lq[1], lq[2], lq[3]),
                                  pack4_s8(lq[4], lq[5], lq[6], lq[7]));
            int kb = hbase >> 7, j = (hbase >> 4) & 7;
            size_t base = (size_t)mt * 65536 + (size_t)kb * 16384 +
                          (size_t)mloc * 128 +
                          (((unsigned)j ^ ((unsigned)mloc & 7)) << 4) + (hbase & 8);
            *(uint2*)(g_A + base) = hi;
            *(uint2*)(g_A + base + 32768) = lo;
        } else if (x_out) {
            float* xp = x_out + (size_t)m * H_ + hbase;
            *(float4*)xp       = make_float4(hv[0], hv[1], hv[2], hv[3]);
            *(float4*)(xp + 4) = make_float4(hv[4], hv[5], hv[6], hv[7]);
        }
    }
#undef ISSUE_CHUNK
}

// ---------------------------------------------------------------------------
// Launch. Output layout: [ x (T*B*H) | h_n (T*L*B*H) | c_n (T*L*B*H) ]
// ---------------------------------------------------------------------------
extern "C" void kernel_launch(void* const* d_in, const int* in_sizes, int n_in,
                              void* d_out, int out_size)
{
    const float* inputs = (const float*)d_in[0];   // [T,B,D]
    const float* h0     = (const float*)d_in[1];   // [L,B,H]
    const float* c0     = (const float*)d_in[2];   // [L,B,H]
    const float* W      = (const float*)d_in[3];   // [L,4,D+H,H]
    const float* bb     = (const float*)d_in[4];   // [L,4,H]

    float* out   = (float*)d_out;
    float* x_out = out;
    float* hn    = out + (size_t)T_ * B_ * H_;
    float* cn    = hn + (size_t)T_ * L_ * B_ * H_;

    cudaFuncSetAttribute(gemm_kernel,
                         cudaFuncAttributeMaxDynamicSharedMemorySize, SMEM_SZ);

    wprep_kernel<<<256, 256>>>(W);        // exactly 65536 work items
    bias_kernel<<<512, 256>>>(h0, W, bb);
    aprep_kernel<<<16384, 256>>>(inputs, B_ * D_);

    dim3 grid(16, M_ / 128);
    // layer 0: per-row A scales; epilogue also writes layer-1's int8 A-image
    gemm_kernel<<<grid, 256, SMEM_SZ>>>(c0, 0, hn, cn, nullptr, 1, 1);
    // layer 1: fixed A scale 1/16256; writes x
    gemm_kernel<<<grid, 256, SMEM_SZ>>>(c0, 1, hn, cn, x_out, 0, 0);
}

// round 12
// speedup vs baseline: 1.9544x; 1.9544x over previous
#include <cuda_runtime.h>
#include <cuda_bf16.h>
#include <cstdint>

// Problem constants
#define T_ 2048
#define B_ 64
#define D_ 256
#define H_ 256
#define L_ 2
#define M_ (T_ * B_)       // 131072 GEMM rows per layer

// W image: per (l, ntile 0..7): 8 blocks (0-3 = W_hi kb0-3, 4-7 = W_lo kb0-3),
// each block 128 n-rows x 64 k bf16 = 16KB, rows 128B, unit swz ((j^(row&7))<<4).
__device__ __align__(16) unsigned char g_W[(size_t)L_ * 8 * 8 * 16384]; // 2 MB
// A image: per m-tile (128 rows): [hi kb0..3 | lo kb0..3], 8 x 16KB = 128KB.
__device__ __align__(16) unsigned char g_A[(size_t)(M_ / 128) * 131072]; // 134 MB
__device__ __align__(16) float4 g_bias4[(size_t)L_ * B_ * H_];          // [l][b][h].(f,i,g,o)

// ---------------------------------------------------------------------------
// helpers
// ---------------------------------------------------------------------------
__device__ __forceinline__ uint32_t smem_u32(const void* p)
{
    uint32_t a;
    asm("{ .reg .u64 t; cvta.to.shared.u64 t, %1; cvt.u32.u64 %0, t; }" : "=r"(a) : "l"(p));
    return a;
}
__device__ __forceinline__ unsigned short bf16_bits(__nv_bfloat16 v)
{
    return *reinterpret_cast<unsigned short*>(&v);
}
__device__ __forceinline__ float sigmoidf_(float x)
{
    return __fdividef(1.0f, 1.0f + __expf(-x));
}
__device__ __forceinline__ float tanhf_(float x)
{
    return 1.0f - __fdividef(2.0f, 1.0f + __expf(2.0f * x));
}
__device__ __forceinline__ uint32_t pack_bf16x2(float a, float b)
{
    __nv_bfloat16 e0 = __float2bfloat16(a);
    __nv_bfloat16 e1 = __float2bfloat16(b);
    return (uint32_t)bf16_bits(e0) | ((uint32_t)bf16_bits(e1) << 16);
}

#define CP16(s, g) asm volatile("cp.async.cg.shared.global [%0], [%1], 16;" :: "r"(s), "l"(g))
#define CP_COMMIT() asm volatile("cp.async.commit_group;" ::: "memory")
#define CP_WAIT1() asm volatile("cp.async.wait_group 1;" ::: "memory")
#define CP_WAIT0() asm volatile("cp.async.wait_group 0;" ::: "memory")

#define LDSM4(r, addr) asm volatile( \
    "ldmatrix.sync.aligned.m8n8.x4.shared.b16 {%0,%1,%2,%3}, [%4];" \
    : "=r"((r)[0]), "=r"((r)[1]), "=r"((r)[2]), "=r"((r)[3]) : "r"(addr))

#define MMA(d, a, b0, b1) asm volatile( \
    "mma.sync.aligned.m16n8k16.row.col.f32.bf16.bf16.f32 " \
    "{%0,%1,%2,%3},{%4,%5,%6,%7},{%8,%9},{%0,%1,%2,%3};" \
    : "+f"((d)[0]), "+f"((d)[1]), "+f"((d)[2]), "+f"((d)[3]) \
    : "r"((a)[0]), "r"((a)[1]), "r"((a)[2]), "r"((a)[3]), "r"(b0), "r"(b1))

// ---------------------------------------------------------------------------
// Kernel 1: W -> bf16 hi/lo image, swizzled 16KB blocks (n = h*4+g interleave)
//   131072 items: j:3 | nloc:7 | blk:3 | nt:3 | l:1
// ---------------------------------------------------------------------------
__global__ void __launch_bounds__(256) wprep_kernel(const float* __restrict__ W)
{
    int idx = blockIdx.x * 256 + threadIdx.x;     // 131072 total
    int j = idx & 7;
    int nloc = (idx >> 3) & 127;
    int rest = idx >> 10;                          // ((l*8+nt)*8 + blk), 0..127
    int blk = rest & 7;
    int nt = (rest >> 3) & 7;
    int l = (rest >> 6) & 1;
    int hl = blk >> 2, kb = blk & 3;
    int n = nt * 128 + nloc, g = n & 3, h = n >> 2;
    int k0 = kb * 64 + j * 8;

    const float* wp = W + ((size_t)(l * 4 + g) * 512 + k0) * 256 + h;
    unsigned short v[8];
#pragma unroll
    for (int i = 0; i < 8; i++) {
        float w = wp[(size_t)i * 256];
        __nv_bfloat16 e = __float2bfloat16(w);
        if (hl)
            e = __float2bfloat16(w - __bfloat162float(e));
        v[i] = bf16_bits(e);
    }
    uint4 out;
    out.x = (uint32_t)v[0] | ((uint32_t)v[1] << 16);
    out.y = (uint32_t)v[2] | ((uint32_t)v[3] << 16);
    out.z = (uint32_t)v[4] | ((uint32_t)v[5] << 16);
    out.w = (uint32_t)v[6] | ((uint32_t)v[7] << 16);
    unsigned off = (unsigned)nloc * 128 + (((unsigned)j ^ ((unsigned)nloc & 7)) << 4);
    *(uint4*)(g_W + (size_t)rest * 16384 + off) = out;
}

// ---------------------------------------------------------------------------
// Kernel 2: A(fp32) -> bf16 hi/lo swizzled image g_A (layer 0 inputs only).
// ---------------------------------------------------------------------------
__global__ void __launch_bounds__(256) aprep_kernel(const float* __restrict__ A, int t_stride)
{
    int idx = blockIdx.x * 256 + threadIdx.x;      // 4,194,304
    int k8 = idx & 31;
    int m = idx >> 5;

    const float* gp = A + (size_t)(m >> 6) * t_stride + (size_t)(m & 63) * 256 + k8 * 8;
    float4 va = *(const float4*)gp;
    float4 vb = *(const float4*)(gp + 4);
    float v[8] = { va.x, va.y, va.z, va.w, vb.x, vb.y, vb.z, vb.w };
    uint32_t hi[4], lo[4];
#pragma unroll
    for (int p = 0; p < 4; p++) {
        float h0f = __bfloat162float(__float2bfloat16(v[2 * p]));
        float h1f = __bfloat162float(__float2bfloat16(v[2 * p + 1]));
        hi[p] = pack_bf16x2(v[2 * p], v[2 * p + 1]);
        lo[p] = pack_bf16x2(v[2 * p] - h0f, v[2 * p + 1] - h1f);
    }
    int mt = m >> 7, mloc = m & 127, kb = k8 >> 3, j = k8 & 7;
    size_t base = (size_t)mt * 131072 + (size_t)kb * 16384 + (size_t)mloc * 128 +
                  (((unsigned)j ^ ((unsigned)mloc & 7)) << 4);
    *(uint4*)(g_A + base) = make_uint4(hi[0], hi[1], hi[2], hi[3]);
    *(uint4*)(g_A + base + 65536) = make_uint4(lo[0], lo[1], lo[2], lo[3]);
}

// ---------------------------------------------------------------------------
// Kernel 3: effective bias (exact fp32): b[l,g,h] + sum_j h0[l,b,j]*W[l,g,D+j,h]
// ---------------------------------------------------------------------------
__global__ void __launch_bounds__(256) bias_kernel(const float* __restrict__ h0,
                                                   const float* __restrict__ W,
                                                   const float* __restrict__ bb)
{
    int idx = blockIdx.x * 256 + threadIdx.x;      // 131072
    int g = idx & 3;
    int h = (idx >> 2) & 255;
    int b = (idx >> 10) & 63;
    int l = (idx >> 16) & 1;

    const float* h0p = h0 + (l * B_ + b) * H_;
    const float* wp  = W + ((size_t)(l * 4 + g) * 512 + 256) * 256 + h;
    float acc = bb[(l * 4 + g) * H_ + h];
#pragma unroll 8
    for (int j = 0; j < H_; j++)
        acc = fmaf(h0p[j], wp[(size_t)j * 256], acc);
    ((float*)g_bias4)[idx] = acc;
}

// ---------------------------------------------------------------------------
// Kernel 4: persistent W-resident HMMA GEMM (3-term bf16) + fused LSTM epilogue.
//   grid (8 nt, 128); CTA pins W(l,nt) = 128KB in smem, loops 8 m-tiles
//   (mt = by + 128*ti).  512 thr = 16 warps (4m x 4n), warp tile 32x32.
//   Per tile: A streams via 3-buf cp.async ring (8 chunks of 16KB, kb-pairs);
//   after last group, next tile's first 3 chunks are issued BEFORE the
//   epilogue so copies land under it.  Epilogue staged in 2 batches of 64 rows.
// ---------------------------------------------------------------------------
#define SM_ARING 131072u
#define SM_STAGE 180224u
#define SMEM_SZ  214016
#define B3(x) ((x) % 3)

__global__ void __launch_bounds__(512, 1)
gemm_kernel(const float* __restrict__ c0, int l,
            float* __restrict__ hn, float* __restrict__ cn,
            float* __restrict__ x_out, int write_a)
{
    extern __shared__ __align__(1024) unsigned char smem[];
    const int tid = threadIdx.x;
    const int nt = blockIdx.x;         // 0..7  (32 h per tile)
    const int by = blockIdx.y;         // 0..127
    const uint32_t su = smem_u32(smem);
    const int lane = tid & 31, wid = tid >> 5;
    const int wm = wid >> 2, wn = wid & 3;
    float* stage = (float*)(smem + SM_STAGE);

    // ---- W load: 128KB once per CTA ----
    {
        const unsigned char* s = g_W + (size_t)(l * 8 + nt) * 131072 + tid * 16;
        uint32_t d = su + tid * 16;
#pragma unroll
        for (int j = 0; j < 16; j++) CP16(d + j * 8192, s + (size_t)j * 8192);
        CP_COMMIT();
    }

#define ISSUE_A(mt, c, buf)                                                       \
    do {                                                                          \
        const unsigned char* sa = g_A + (size_t)(mt) * 131072 +                   \
            ((c) & 1) * 65536 + ((c) >> 1) * 16384 + tid * 16;                    \
        uint32_t da = su + SM_ARING + (uint32_t)(buf) * 16384u + tid * 16;        \
        CP16(da, sa); CP16(da + 8192, sa + 8192);                                 \
        CP_COMMIT();                                                              \
    } while (0)

    // per-lane ldmatrix offsets
    uint32_t aoff[2], aswz[2], boff[2], bswz[2];
    const uint32_t ua = (uint32_t)(lane >> 4);
    const uint32_t ub = (uint32_t)((lane >> 3) & 1);
#pragma unroll
    for (int tm = 0; tm < 2; tm++) {
        uint32_t row = (uint32_t)(wm * 32 + tm * 16 + (lane & 15));
        aoff[tm] = row * 128u;
        aswz[tm] = row & 7u;
    }
#pragma unroll
    for (int tn = 0; tn < 2; tn++) {
        uint32_t row = (uint32_t)(wn * 32 + tn * 16 + (lane & 7) + ((lane >> 4) << 3));
        boff[tn] = row * 128u;
        bswz[tn] = row & 7u;
    }

    // prologue: first tile's chunks 0,1,2
    int cb = 0;                          // ring buf of current tile's chunk 0
    ISSUE_A(by, 0, 0);
    ISSUE_A(by, 1, 1);
    ISSUE_A(by, 2, 2);

#pragma unroll 1
    for (int ti = 0; ti < 8; ti++) {
        const int mt = by + ti * 128;
        const int m0 = mt * 128;

        float acc[2][4][4];
#pragma unroll
        for (int i = 0; i < 2; i++)
#pragma unroll
            for (int j = 0; j < 4; j++)
#pragma unroll
                for (int q = 0; q < 4; q++) acc[i][j][q] = 0.0f;

#pragma unroll
        for (int kb = 0; kb < 4; kb++) {
            if (kb < 3) { CP_WAIT1(); } else { CP_WAIT0(); }
            __syncthreads();

            const int bufE = B3(cb + 2 * kb);
            const int bufO = B3(cb + 2 * kb + 1);
            const uint32_t be = su + SM_ARING + (uint32_t)bufE * 16384u;
            const uint32_t bo = su + SM_ARING + (uint32_t)bufO * 16384u;
            const uint32_t wh = su + (uint32_t)kb * 16384u;
            const uint32_t wl = su + (uint32_t)(4 + kb) * 16384u;

#pragma unroll
            for (int ks = 0; ks < 4; ks++) {
                uint32_t ah[2][4], al[2][4], w[2][4];
                const uint32_t ka = (uint32_t)(ks * 2) + ua;
                const uint32_t kv = (uint32_t)(ks * 2) + ub;

#pragma unroll
                for (int tm = 0; tm < 2; tm++)
                    LDSM4(ah[tm], be + aoff[tm] + ((ka ^ aswz[tm]) << 4));
#pragma unroll
                for (int tn = 0; tn < 2; tn++)
                    LDSM4(w[tn], wh + boff[tn] + ((kv ^ bswz[tn]) << 4));
#pragma unroll
                for (int tm = 0; tm < 2; tm++)
#pragma unroll
                    for (int tn = 0; tn < 2; tn++) {
                        MMA(acc[tm][tn * 2 + 0], ah[tm], w[tn][0], w[tn][1]);
                        MMA(acc[tm][tn * 2 + 1], ah[tm], w[tn][2], w[tn][3]);
                    }

#pragma unroll
                for (int tm = 0; tm < 2; tm++)
                    LDSM4(al[tm], bo + aoff[tm] + ((ka ^ aswz[tm]) << 4));
#pragma unroll
                for (int tm = 0; tm < 2; tm++)
#pragma unroll
                    for (int tn = 0; tn < 2; tn++) {
                        MMA(acc[tm][tn * 2 + 0], al[tm], w[tn][0], w[tn][1]);
                        MMA(acc[tm][tn * 2 + 1], al[tm], w[tn][2], w[tn][3]);
                    }

#pragma unroll
                for (int tn = 0; tn < 2; tn++)
                    LDSM4(w[tn], wl + boff[tn] + ((kv ^ bswz[tn]) << 4));
#pragma unroll
                for (int tm = 0; tm < 2; tm++)
#pragma unroll
                    for (int tn = 0; tn < 2; tn++) {
                        MMA(acc[tm][tn * 2 + 0], ah[tm], w[tn][0], w[tn][1]);
                        MMA(acc[tm][tn * 2 + 1], ah[tm], w[tn][2], w[tn][3]);
                    }
            }
            __syncthreads();

            // refill freed buffers
            if (kb == 0) {
                ISSUE_A(mt, 3, B3(cb + 3)); ISSUE_A(mt, 4, B3(cb + 4));
            } else if (kb == 1) {
                ISSUE_A(mt, 5, B3(cb + 5)); ISSUE_A(mt, 6, B3(cb + 6));
            } else if (kb == 2) {
                ISSUE_A(mt, 7, B3(cb + 7));
            } else if (ti < 7) {
                int nmt = mt + 128;
                ISSUE_A(nmt, 0, B3(cb + 8));
                ISSUE_A(nmt, 1, B3(cb + 9));
                ISSUE_A(nmt, 2, B3(cb + 10));
            }
        }
        cb = B3(cb + 2);

        // ---- staged epilogue: 2 batches of 64 rows (overlaps the copies) ----
#pragma unroll 1
        for (int bat = 0; bat < 2; bat++) {
            if ((wm >> 1) == bat) {
                const int r0 = lane >> 2, cp2 = (lane & 3) * 2;
                const int wml = wm & 1;
#pragma unroll
                for (int tm = 0; tm < 2; tm++) {
                    int mr = wml * 32 + tm * 16 + r0;
#pragma unroll
                    for (int j = 0; j < 4; j++) {
                        int nc = wn * 32 + j * 8 + cp2;
                        stage[mr * 132 + nc]           = acc[tm][j][0];
                        stage[mr * 132 + nc + 1]       = acc[tm][j][1];
                        stage[(mr + 8) * 132 + nc]     = acc[tm][j][2];
                        stage[(mr + 8) * 132 + nc + 1] = acc[tm][j][3];
                    }
                }
            }
            __syncthreads();

#pragma unroll
            for (int u = 0; u < 4; u++) {
                int item = u * 512 + tid;       // 2048 items
                int hloc = item & 31, rloc = item >> 5;
                int row = bat * 64 + rloc;
                int m = m0 + row;
                int t = m >> 6, b = m & 63;
                int h = nt * 32 + hloc;

                float4 pre = *(const float4*)&stage[rloc * 132 + hloc * 4];
                float4 bv = g_bias4[(size_t)(l * B_ + b) * H_ + h];
                float f  = sigmoidf_(pre.x + bv.x);
                float ii = sigmoidf_(pre.y + bv.y);
                float gt = tanhf_(pre.z + bv.z);
                float o  = sigmoidf_(pre.w + bv.w);
                float cc = fmaf(f, c0[((size_t)l * B_ + b) * H_ + h], ii * gt);
                float hv = o * tanhf_(cc);

                size_t ob = ((size_t)t * (L_ * B_) + (size_t)l * B_ + b) * H_ + h;
                hn[ob] = hv;
                cn[ob] = cc;

                if (write_a) {
                    // emit bf16 hi/lo A-image element (k = h) for layer 1
                    __nv_bfloat16 e = __float2bfloat16(hv);
                    __nv_bfloat16 r = __float2bfloat16(hv - __bfloat162float(e));
                    int kb_a = h >> 6, j_a = (h >> 3) & 7;
                    size_t base = (size_t)mt * 131072 + (size_t)kb_a * 16384 +
                                  (size_t)row * 128 +
                                  (((unsigned)j_a ^ ((unsigned)row & 7)) << 4) +
                                  (unsigned)(h & 7) * 2;
                    *(__nv_bfloat16*)(g_A + base) = e;
                    *(__nv_bfloat16*)(g_A + base + 65536) = r;
                } else if (x_out) {
                    x_out[(size_t)m * H_ + h] = hv;
                }
            }
            __syncthreads();
        }
    }
#undef ISSUE_A
}

// ---------------------------------------------------------------------------
// Launch. Output layout: [ x (T*B*H) | h_n (T*L*B*H) | c_n (T*L*B*H) ]
// ---------------------------------------------------------------------------
extern "C" void kernel_launch(void* const* d_in, const int* in_sizes, int n_in,
                              void* d_out, int out_size)
{
    const float* inputs = (const float*)d_in[0];   // [T,B,D]
    const float* h0     = (const float*)d_in[1];   // [L,B,H]
    const float* c0     = (const float*)d_in[2];   // [L,B,H]
    const float* W      = (const float*)d_in[3];   // [L,4,D+H,H]
    const float* bb     = (const float*)d_in[4];   // [L,4,H]

    float* out   = (float*)d_out;
    float* x_out = out;
    float* hn    = out + (size_t)T_ * B_ * H_;
    float* cn    = hn + (size_t)T_ * L_ * B_ * H_;

    cudaFuncSetAttribute(gemm_kernel,
                         cudaFuncAttributeMaxDynamicSharedMemorySize, SMEM_SZ);

    wprep_kernel<<<512, 256>>>(W);
    bias_kernel<<<512, 256>>>(h0, W, bb);
    aprep_kernel<<<16384, 256>>>(inputs, B_ * D_);

    dim3 grid(8, 128);
    // layer 0: epilogue also writes layer-1's bf16 A-image
    gemm_kernel<<<grid, 512, SMEM_SZ>>>(c0, 0, hn, cn, nullptr, 1);
    // layer 1: writes x
    gemm_kernel<<<grid, 512, SMEM_SZ>>>(c0, 1, hn, cn, x_out, 0);
}

// round 13
// speedup vs baseline: 1.9780x; 1.0120x over previous
#include <cuda_runtime.h>
#include <cuda_bf16.h>
#include <cstdint>

// Problem constants
#define T_ 2048
#define B_ 64
#define D_ 256
#define H_ 256
#define L_ 2
#define M_ (T_ * B_)       // 131072 GEMM rows per layer

// W image: per (l, ntile 0..15): 8 blocks [hl 0..1][kb 0..3],
// each block 64 n-rows x 64 k bf16 = 8KB, rows 128B, unit swz ((j^(row&7))<<4).
__device__ __align__(16) unsigned char g_W[(size_t)L_ * 16 * 8 * 8192];  // 2 MB
// A image: per m-tile (128 rows): [hi kb0..3 | lo kb0..3], 8 x 16KB = 128KB.
__device__ __align__(16) unsigned char g_A[(size_t)(M_ / 128) * 131072]; // 134 MB
__device__ __align__(16) float4 g_bias4[(size_t)L_ * B_ * H_];           // [l][b][h].(f,i,g,o)

// ---------------------------------------------------------------------------
// helpers
// ---------------------------------------------------------------------------
__device__ __forceinline__ uint32_t smem_u32(const void* p)
{
    uint32_t a;
    asm("{ .reg .u64 t; cvta.to.shared.u64 t, %1; cvt.u32.u64 %0, t; }" : "=r"(a) : "l"(p));
    return a;
}
__device__ __forceinline__ unsigned short bf16_bits(__nv_bfloat16 v)
{
    return *reinterpret_cast<unsigned short*>(&v);
}
__device__ __forceinline__ float sigmoidf_(float x)
{
    return __fdividef(1.0f, 1.0f + __expf(-x));
}
__device__ __forceinline__ float tanhf_(float x)
{
    return 1.0f - __fdividef(2.0f, 1.0f + __expf(2.0f * x));
}
__device__ __forceinline__ uint32_t pack_bf16x2(float a, float b)
{
    __nv_bfloat16 e0 = __float2bfloat16(a);
    __nv_bfloat16 e1 = __float2bfloat16(b);
    return (uint32_t)bf16_bits(e0) | ((uint32_t)bf16_bits(e1) << 16);
}

#define CP16(s, g) asm volatile("cp.async.cg.shared.global [%0], [%1], 16;" :: "r"(s), "l"(g))
#define CP_COMMIT() asm volatile("cp.async.commit_group;" ::: "memory")
#define CP_WAIT1() asm volatile("cp.async.wait_group 1;" ::: "memory")
#define CP_WAIT0() asm volatile("cp.async.wait_group 0;" ::: "memory")

#define LDSM4(r, addr) asm volatile( \
    "ldmatrix.sync.aligned.m8n8.x4.shared.b16 {%0,%1,%2,%3}, [%4];" \
    : "=r"((r)[0]), "=r"((r)[1]), "=r"((r)[2]), "=r"((r)[3]) : "r"(addr))

#define MMA(d, a, b0, b1) asm volatile( \
    "mma.sync.aligned.m16n8k16.row.col.f32.bf16.bf16.f32 " \
    "{%0,%1,%2,%3},{%4,%5,%6,%7},{%8,%9},{%0,%1,%2,%3};" \
    : "+f"((d)[0]), "+f"((d)[1]), "+f"((d)[2]), "+f"((d)[3]) \
    : "r"((a)[0]), "r"((a)[1]), "r"((a)[2]), "r"((a)[3]), "r"(b0), "r"(b1))

// ---------------------------------------------------------------------------
// Kernel 1: W -> bf16 hi/lo image, 8KB blocks (n = h*4+g gate interleave).
//   131072 items: j:3 | nloc:6 | kb:2 | hl:1 | nt:4 | l:1
// ---------------------------------------------------------------------------
__global__ void __launch_bounds__(256) wprep_kernel(const float* __restrict__ W)
{
    int idx = blockIdx.x * 256 + threadIdx.x;     // 131072 total
    int j = idx & 7;
    int nloc = (idx >> 3) & 63;
    int kb = (idx >> 9) & 3;
    int hl = (idx >> 11) & 1;
    int nt = (idx >> 12) & 15;
    int l = (idx >> 16) & 1;

    int n = nt * 64 + nloc, g = n & 3, h = n >> 2;
    int k0 = kb * 64 + j * 8;
    const float* wp = W + ((size_t)(l * 4 + g) * 512 + k0) * 256 + h;

    unsigned short v[8];
#pragma unroll
    for (int i = 0; i < 8; i++) {
        float w = wp[(size_t)i * 256];
        __nv_bfloat16 e = __float2bfloat16(w);
        if (hl)
            e = __float2bfloat16(w - __bfloat162float(e));
        v[i] = bf16_bits(e);
    }
    uint4 out;
    out.x = (uint32_t)v[0] | ((uint32_t)v[1] << 16);
    out.y = (uint32_t)v[2] | ((uint32_t)v[3] << 16);
    out.z = (uint32_t)v[4] | ((uint32_t)v[5] << 16);
    out.w = (uint32_t)v[6] | ((uint32_t)v[7] << 16);
    unsigned off = (unsigned)nloc * 128 + (((unsigned)j ^ ((unsigned)nloc & 7)) << 4);
    size_t blk = ((size_t)(l * 16 + nt) * 8 + hl * 4 + kb);
    *(uint4*)(g_W + blk * 8192 + off) = out;
}

// ---------------------------------------------------------------------------
// Kernel 2: A(fp32) -> bf16 hi/lo swizzled image g_A (layer 0 inputs only).
// ---------------------------------------------------------------------------
__global__ void __launch_bounds__(256) aprep_kernel(const float* __restrict__ A, int t_stride)
{
    int idx = blockIdx.x * 256 + threadIdx.x;      // 4,194,304
    int k8 = idx & 31;
    int m = idx >> 5;

    const float* gp = A + (size_t)(m >> 6) * t_stride + (size_t)(m & 63) * 256 + k8 * 8;
    float4 va = *(const float4*)gp;
    float4 vb = *(const float4*)(gp + 4);
    float v[8] = { va.x, va.y, va.z, va.w, vb.x, vb.y, vb.z, vb.w };
    uint32_t hi[4], lo[4];
#pragma unroll
    for (int p = 0; p < 4; p++) {
        float h0f = __bfloat162float(__float2bfloat16(v[2 * p]));
        float h1f = __bfloat162float(__float2bfloat16(v[2 * p + 1]));
        hi[p] = pack_bf16x2(v[2 * p], v[2 * p + 1]);
        lo[p] = pack_bf16x2(v[2 * p] - h0f, v[2 * p + 1] - h1f);
    }
    int mt = m >> 7, mloc = m & 127, kb = k8 >> 3, j = k8 & 7;
    size_t base = (size_t)mt * 131072 + (size_t)kb * 16384 + (size_t)mloc * 128 +
                  (((unsigned)j ^ ((unsigned)mloc & 7)) << 4);
    *(uint4*)(g_A + base) = make_uint4(hi[0], hi[1], hi[2], hi[3]);
    *(uint4*)(g_A + base + 65536) = make_uint4(lo[0], lo[1], lo[2], lo[3]);
}

// ---------------------------------------------------------------------------
// Kernel 3: effective bias (exact fp32): b[l,g,h] + sum_j h0[l,b,j]*W[l,g,D+j,h]
// ---------------------------------------------------------------------------
__global__ void __launch_bounds__(256) bias_kernel(const float* __restrict__ h0,
                                                   const float* __restrict__ W,
                                                   const float* __restrict__ bb)
{
    int idx = blockIdx.x * 256 + threadIdx.x;      // 131072
    int g = idx & 3;
    int h = (idx >> 2) & 255;
    int b = (idx >> 10) & 63;
    int l = (idx >> 16) & 1;

    const float* h0p = h0 + (l * B_ + b) * H_;
    const float* wp  = W + ((size_t)(l * 4 + g) * 512 + 256) * 256 + h;
    float acc = bb[(l * 4 + g) * H_ + h];
#pragma unroll 8
    for (int j = 0; j < H_; j++)
        acc = fmaf(h0p[j], wp[(size_t)j * 256], acc);
    ((float*)g_bias4)[idx] = acc;
}

// ---------------------------------------------------------------------------
// Kernel 4: HMMA GEMM (3-term bf16 split) + fused LSTM epilogue.
//   CTA: 128m x 64n (16 h), 256 thr = 8 warps (4m x 2n), warp tile 32x32.
//   3 CTAs/SM (regs <= 84, smem 72KB): cross-CTA overlap hides epilogue/LDSM.
//   Chunks c 0..7: hl=c&1, kb=c>>1; chunk = [A 16KB | W 8KB] = 24KB, ring of 3.
//   kb-group g consumes chunks 2g (Ah,Wh), 2g+1 (Al,Wl) with register reuse.
//   grid: x = nt 0..15 (16 h each), y = mt 0..1023.
// ---------------------------------------------------------------------------
#define CHUNK_BYTES 24576u
#define SMEM_SZ 73728
#define B3(x) ((x) % 3)

__global__ void __launch_bounds__(256, 3)
gemm_kernel(const float* __restrict__ c0, int l,
            float* __restrict__ hn, float* __restrict__ cn,
            float* __restrict__ x_out, int write_a)
{
    extern __shared__ __align__(1024) unsigned char smem[];
    const int tid = threadIdx.x;
    const int nt = blockIdx.x;
    const int mt = blockIdx.y;
    const int m0 = mt * 128;
    const uint32_t su = smem_u32(smem);
    const int lane = tid & 31, wid = tid >> 5;
    const int wm = wid >> 1, wn = wid & 1;

    const unsigned char* gWb = g_W + (size_t)(l * 16 + nt) * 65536;
    const unsigned char* gAb = g_A + (size_t)mt * 131072;

#define ISSUE_CHUNK(c, buf)                                                     \
    do {                                                                        \
        int hl_ = (c) & 1, kb_ = (c) >> 1;                                      \
        const unsigned char* sa = gAb + hl_ * 65536 + kb_ * 16384 + tid * 16;   \
        const unsigned char* sb = gWb + (size_t)(hl_ * 4 + kb_) * 8192 + tid * 16; \
        uint32_t da = su + (buf) * CHUNK_BYTES + tid * 16;                      \
        uint32_t db = da + 16384u;                                              \
        CP16(da, sa); CP16(da + 4096, sa + 4096);                               \
        CP16(da + 8192, sa + 8192); CP16(da + 12288, sa + 12288);               \
        CP16(db, sb); CP16(db + 4096, sb + 4096);                               \
        CP_COMMIT();                                                            \
    } while (0)

    // prologue: prefill chunks 0, 1, 2
    ISSUE_CHUNK(0, 0);
    ISSUE_CHUNK(1, 1);
    ISSUE_CHUNK(2, 2);

    // per-lane ldmatrix offsets
    uint32_t aoff[2], aswz[2], boff[2], bswz[2];
    const uint32_t ua = (uint32_t)(lane >> 4);
    const uint32_t ub = (uint32_t)((lane >> 3) & 1);
#pragma unroll
    for (int tm = 0; tm < 2; tm++) {
        uint32_t row = (uint32_t)(wm * 32 + tm * 16 + (lane & 15));
        aoff[tm] = row * 128u;
        aswz[tm] = row & 7u;
    }
#pragma unroll
    for (int tn = 0; tn < 2; tn++) {
        uint32_t row = (uint32_t)(wn * 32 + tn * 16 + (lane & 7) + ((lane >> 4) << 3));
        boff[tn] = row * 128u + 16384u;           // W region inside chunk
        bswz[tn] = row & 7u;
    }

    float acc[2][4][4];
#pragma unroll
    for (int i = 0; i < 2; i++)
#pragma unroll
        for (int j = 0; j < 4; j++)
#pragma unroll
            for (int q = 0; q < 4; q++) acc[i][j][q] = 0.0f;

    // mainloop: 4 kb-groups, each = 2 chunks (even: Ah|Wh, odd: Al|Wl)
#pragma unroll 1
    for (int g = 0; g < 4; g++) {
        if (g == 3) { CP_WAIT0(); } else { CP_WAIT1(); }
        __syncthreads();

        const int ce = 2 * g;
        const uint32_t be = su + (uint32_t)B3(ce) * CHUNK_BYTES;       // Ah|Wh
        const uint32_t bo = su + (uint32_t)B3(ce + 1) * CHUNK_BYTES;   // Al|Wl

#pragma unroll
        for (int ks = 0; ks < 4; ks++) {
            uint32_t ah[2][4], al[2][4], w[2][4];
            const uint32_t ka = (uint32_t)(ks * 2) + ua;
            const uint32_t kv = (uint32_t)(ks * 2) + ub;

            // term 1: Ah * Wh
#pragma unroll
            for (int tm = 0; tm < 2; tm++)
                LDSM4(ah[tm], be + aoff[tm] + ((ka ^ aswz[tm]) << 4));
#pragma unroll
            for (int tn = 0; tn < 2; tn++)
                LDSM4(w[tn], be + boff[tn] + ((kv ^ bswz[tn]) << 4));
#pragma unroll
            for (int tm = 0; tm < 2; tm++)
#pragma unroll
                for (int tn = 0; tn < 2; tn++) {
                    MMA(acc[tm][tn * 2 + 0], ah[tm], w[tn][0], w[tn][1]);
                    MMA(acc[tm][tn * 2 + 1], ah[tm], w[tn][2], w[tn][3]);
                }

            // term 2: Al * Wh (Wh still in regs)
#pragma unroll
            for (int tm = 0; tm < 2; tm++)
                LDSM4(al[tm], bo + aoff[tm] + ((ka ^ aswz[tm]) << 4));
#pragma unroll
            for (int tm = 0; tm < 2; tm++)
#pragma unroll
                for (int tn = 0; tn < 2; tn++) {
                    MMA(acc[tm][tn * 2 + 0], al[tm], w[tn][0], w[tn][1]);
                    MMA(acc[tm][tn * 2 + 1], al[tm], w[tn][2], w[tn][3]);
                }

            // term 3: Ah * Wl (Ah still in regs; Wl overwrites Wh regs)
#pragma unroll
            for (int tn = 0; tn < 2; tn++)
                LDSM4(w[tn], bo + boff[tn] + ((kv ^ bswz[tn]) << 4));
#pragma unroll
            for (int tm = 0; tm < 2; tm++)
#pragma unroll
                for (int tn = 0; tn < 2; tn++) {
                    MMA(acc[tm][tn * 2 + 0], ah[tm], w[tn][0], w[tn][1]);
                    MMA(acc[tm][tn * 2 + 1], ah[tm], w[tn][2], w[tn][3]);
                }
        }
        __syncthreads();

        // refill freed buffers (both chunks of the group just consumed)
        if (g == 0) { ISSUE_CHUNK(3, B3(3)); ISSUE_CHUNK(4, B3(4)); }
        else if (g == 1) { ISSUE_CHUNK(5, B3(5)); ISSUE_CHUNK(6, B3(6)); }
        else if (g == 2) { ISSUE_CHUNK(7, B3(7)); }
    }

    // stage accumulators to smem (128 rows x 64 cols, row pad 68 floats)
    {
        float* stage = (float*)smem;
        const int r0 = lane >> 2, cp2 = (lane & 3) * 2;
#pragma unroll
        for (int tm = 0; tm < 2; tm++) {
            int mr = wm * 32 + tm * 16 + r0;
#pragma unroll
            for (int j = 0; j < 4; j++) {
                int nc = wn * 32 + j * 8 + cp2;
                stage[mr * 68 + nc]           = acc[tm][j][0];
                stage[mr * 68 + nc + 1]       = acc[tm][j][1];
                stage[(mr + 8) * 68 + nc]     = acc[tm][j][2];
                stage[(mr + 8) * 68 + nc + 1] = acc[tm][j][3];
            }
        }
    }
    __syncthreads();

    // fused LSTM epilogue: 256 items = 128 rows x 2 half-rows (8 h each)
    {
        const float* stage = (const float*)smem;
        int hu = tid & 1, mloc = tid >> 1;
        int m = m0 + mloc;
        int t = m >> 6, b = m & 63;
        int hbase = nt * 16 + hu * 8;

        const float4* bp = g_bias4 + (size_t)(l * B_ + b) * H_ + hbase;
        const float* c0p = c0 + ((size_t)l * B_ + b) * H_ + hbase;
        float hv[8], cc[8];
#pragma unroll
        for (int q = 0; q < 8; q++) {
            float4 pre = *(const float4*)&stage[mloc * 68 + (hu * 8 + q) * 4];
            float4 bv = bp[q];
            float f  = sigmoidf_(pre.x + bv.x);
            float ii = sigmoidf_(pre.y + bv.y);
            float gt = tanhf_(pre.z + bv.z);
            float o  = sigmoidf_(pre.w + bv.w);
            cc[q] = fmaf(f, c0p[q], ii * gt);
            hv[q] = o * tanhf_(cc[q]);
        }
        size_t ob = ((size_t)t * (L_ * B_) + (size_t)l * B_ + b) * H_ + hbase;
        *(float4*)&hn[ob]     = make_float4(hv[0], hv[1], hv[2], hv[3]);
        *(float4*)&hn[ob + 4] = make_float4(hv[4], hv[5], hv[6], hv[7]);
        *(float4*)&cn[ob]     = make_float4(cc[0], cc[1], cc[2], cc[3]);
        *(float4*)&cn[ob + 4] = make_float4(cc[4], cc[5], cc[6], cc[7]);

        if (write_a) {
            // emit bf16 hi/lo A-image unit (8 h = one 16B unit) for layer 1
            uint32_t hi[4], lo[4];
#pragma unroll
            for (int p = 0; p < 4; p++) {
                float h0f = __bfloat162float(__float2bfloat16(hv[2 * p]));
                float h1f = __bfloat162float(__float2bfloat16(hv[2 * p + 1]));
                hi[p] = pack_bf16x2(hv[2 * p], hv[2 * p + 1]);
                lo[p] = pack_bf16x2(hv[2 * p] - h0f, hv[2 * p + 1] - h1f);
            }
            int kb_a = hbase >> 6, j_a = (hbase >> 3) & 7;
            size_t base = (size_t)mt * 131072 + (size_t)kb_a * 16384 +
                          (size_t)mloc * 128 +
                          (((unsigned)j_a ^ ((unsigned)mloc & 7)) << 4);
            *(uint4*)(g_A + base)         = make_uint4(hi[0], hi[1], hi[2], hi[3]);
            *(uint4*)(g_A + base + 65536) = make_uint4(lo[0], lo[1], lo[2], lo[3]);
        } else if (x_out) {
            float* xp = x_out + (size_t)m * H_ + hbase;
            *(float4*)xp       = make_float4(hv[0], hv[1], hv[2], hv[3]);
            *(float4*)(xp + 4) = make_float4(hv[4], hv[5], hv[6], hv[7]);
        }
    }
#undef ISSUE_CHUNK
}

// ---------------------------------------------------------------------------
// Launch. Output layout: [ x (T*B*H) | h_n (T*L*B*H) | c_n (T*L*B*H) ]
// ---------------------------------------------------------------------------
extern "C" void kernel_launch(void* const* d_in, const int* in_sizes, int n_in,
                              void* d_out, int out_size)
{
    const float* inputs = (const float*)d_in[0];   // [T,B,D]
    const float* h0     = (const float*)d_in[1];   // [L,B,H]
    const float* c0     = (const float*)d_in[2];   // [L,B,H]
    const float* W      = (const float*)d_in[3];   // [L,4,D+H,H]
    const float* bb     = (const float*)d_in[4];   // [L,4,H]

    float* out   = (float*)d_out;
    float* x_out = out;
    float* hn    = out + (size_t)T_ * B_ * H_;
    float* cn    = hn + (size_t)T_ * L_ * B_ * H_;

    cudaFuncSetAttribute(gemm_kernel,
                         cudaFuncAttributeMaxDynamicSharedMemorySize, SMEM_SZ);

    wprep_kernel<<<512, 256>>>(W);
    bias_kernel<<<512, 256>>>(h0, W, bb);
    aprep_kernel<<<16384, 256>>>(inputs, B_ * D_);

    dim3 grid(16, M_ / 128);
    // layer 0: epilogue also writes layer-1's bf16 A-image
    gemm_kernel<<<grid, 256, SMEM_SZ>>>(c0, 0, hn, cn, nullptr, 1);
    // layer 1: writes x
    gemm_kernel<<<grid, 256, SMEM_SZ>>>(c0, 1, hn, cn, x_out, 0);
}

// round 14
// speedup vs baseline: 2.9590x; 1.4960x over previous
#include <cuda_runtime.h>
#include <cuda_fp16.h>
#include <cstdint>

// Problem constants
#define T_ 2048
#define B_ 64
#define D_ 256
#define H_ 256
#define L_ 2
#define M_ (T_ * B_)       // 131072 GEMM rows per layer

// W image (single fp16): per (l, ntile 0..7): 4 kb-blocks,
// each block 128 n-rows x 64 k fp16 = 16KB, rows 128B, unit swz ((j^(row&7))<<4).
__device__ __align__(16) unsigned char g_W[(size_t)L_ * 8 * 4 * 16384]; // 1 MB
// A image (fp16 hi/lo): per m-tile (128 rows): [hi kb0..3 | lo kb0..3] = 128KB.
__device__ __align__(16) unsigned char g_A[(size_t)(M_ / 128) * 131072]; // 134 MB
__device__ __align__(16) float4 g_bias4[(size_t)L_ * B_ * H_];          // [l][b][h].(f,i,g,o)

// ---------------------------------------------------------------------------
// helpers
// ---------------------------------------------------------------------------
__device__ __forceinline__ uint32_t smem_u32(const void* p)
{
    uint32_t a;
    asm("{ .reg .u64 t; cvta.to.shared.u64 t, %1; cvt.u32.u64 %0, t; }" : "=r"(a) : "l"(p));
    return a;
}
__device__ __forceinline__ unsigned short fp16_bits(float v)
{
    __half h = __float2half_rn(v);
    return *reinterpret_cast<unsigned short*>(&h);
}
__device__ __forceinline__ float fp16_val(float v)
{
    return __half2float(__float2half_rn(v));
}
__device__ __forceinline__ uint32_t pack_fp16x2(float a, float b)
{
    __half2 h = __floats2half2_rn(a, b);
    return *reinterpret_cast<uint32_t*>(&h);
}
__device__ __forceinline__ float sigmoidf_(float x)
{
    return __fdividef(1.0f, 1.0f + __expf(-x));
}
__device__ __forceinline__ float tanhf_(float x)
{
    return 1.0f - __fdividef(2.0f, 1.0f + __expf(2.0f * x));
}

#define CP16(s, g) asm volatile("cp.async.cg.shared.global [%0], [%1], 16;" :: "r"(s), "l"(g))
#define CP_COMMIT() asm volatile("cp.async.commit_group;" ::: "memory")
#define CP_WAIT1() asm volatile("cp.async.wait_group 1;" ::: "memory")
#define CP_WAIT0() asm volatile("cp.async.wait_group 0;" ::: "memory")

#define LDSM4(r, addr) asm volatile( \
    "ldmatrix.sync.aligned.m8n8.x4.shared.b16 {%0,%1,%2,%3}, [%4];" \
    : "=r"((r)[0]), "=r"((r)[1]), "=r"((r)[2]), "=r"((r)[3]) : "r"(addr))

#define MMA(d, a, b0, b1) asm volatile( \
    "mma.sync.aligned.m16n8k16.row.col.f32.f16.f16.f32 " \
    "{%0,%1,%2,%3},{%4,%5,%6,%7},{%8,%9},{%0,%1,%2,%3};" \
    : "+f"((d)[0]), "+f"((d)[1]), "+f"((d)[2]), "+f"((d)[3]) \
    : "r"((a)[0]), "r"((a)[1]), "r"((a)[2]), "r"((a)[3]), "r"(b0), "r"(b1))

// ---------------------------------------------------------------------------
// Kernel 1: W -> single fp16 image, swizzled 16KB blocks (n = h*4+g interleave)
//   EXACTLY 65536 items (256 blocks): j:3 | nloc:7 | kb:2 | nt:3 | l:1
// ---------------------------------------------------------------------------
__global__ void __launch_bounds__(256) wprep_kernel(const float* __restrict__ W)
{
    int idx = blockIdx.x * 256 + threadIdx.x;      // 65536 total
    int j = idx & 7;
    int nloc = (idx >> 3) & 127;
    int kb = (idx >> 10) & 3;
    int nt = (idx >> 12) & 7;
    int l = (idx >> 15) & 1;

    int n = nt * 128 + nloc, g = n & 3, h = n >> 2;
    int k0 = kb * 64 + j * 8;
    const float* wp = W + ((size_t)(l * 4 + g) * 512 + k0) * 256 + h;

    unsigned short v[8];
#pragma unroll
    for (int i = 0; i < 8; i++)
        v[i] = fp16_bits(wp[(size_t)i * 256]);

    uint4 out;
    out.x = (uint32_t)v[0] | ((uint32_t)v[1] << 16);
    out.y = (uint32_t)v[2] | ((uint32_t)v[3] << 16);
    out.z = (uint32_t)v[4] | ((uint32_t)v[5] << 16);
    out.w = (uint32_t)v[6] | ((uint32_t)v[7] << 16);
    unsigned off = (unsigned)nloc * 128 + (((unsigned)j ^ ((unsigned)nloc & 7)) << 4);
    size_t blk = (size_t)(l * 8 + nt) * 4 + kb;
    *(uint4*)(g_W + blk * 16384 + off) = out;
}

// ---------------------------------------------------------------------------
// Kernel 2: A(fp32) -> fp16 hi/lo swizzled image g_A (layer 0 inputs only).
// ---------------------------------------------------------------------------
__global__ void __launch_bounds__(256) aprep_kernel(const float* __restrict__ A, int t_stride)
{
    int idx = blockIdx.x * 256 + threadIdx.x;      // 4,194,304
    int k8 = idx & 31;
    int m = idx >> 5;

    const float* gp = A + (size_t)(m >> 6) * t_stride + (size_t)(m & 63) * 256 + k8 * 8;
    float4 va = *(const float4*)gp;
    float4 vb = *(const float4*)(gp + 4);
    float v[8] = { va.x, va.y, va.z, va.w, vb.x, vb.y, vb.z, vb.w };
    uint32_t hi[4], lo[4];
#pragma unroll
    for (int p = 0; p < 4; p++) {
        float h0f = fp16_val(v[2 * p]);
        float h1f = fp16_val(v[2 * p + 1]);
        hi[p] = pack_fp16x2(v[2 * p], v[2 * p + 1]);
        lo[p] = pack_fp16x2(v[2 * p] - h0f, v[2 * p + 1] - h1f);
    }
    int mt = m >> 7, mloc = m & 127, kb = k8 >> 3, j = k8 & 7;
    size_t base = (size_t)mt * 131072 + (size_t)kb * 16384 + (size_t)mloc * 128 +
                  (((unsigned)j ^ ((unsigned)mloc & 7)) << 4);
    *(uint4*)(g_A + base) = make_uint4(hi[0], hi[1], hi[2], hi[3]);
    *(uint4*)(g_A + base + 65536) = make_uint4(lo[0], lo[1], lo[2], lo[3]);
}

// ---------------------------------------------------------------------------
// Kernel 3: effective bias (exact fp32): b[l,g,h] + sum_j h0[l,b,j]*W[l,g,D+j,h]
// ---------------------------------------------------------------------------
__global__ void __launch_bounds__(256) bias_kernel(const float* __restrict__ h0,
                                                   const float* __restrict__ W,
                                                   const float* __restrict__ bb)
{
    int idx = blockIdx.x * 256 + threadIdx.x;      // 131072
    int g = idx & 3;
    int h = (idx >> 2) & 255;
    int b = (idx >> 10) & 63;
    int l = (idx >> 16) & 1;

    const float* h0p = h0 + (l * B_ + b) * H_;
    const float* wp  = W + ((size_t)(l * 4 + g) * 512 + 256) * 256 + h;
    float acc = bb[(l * 4 + g) * H_ + h];
#pragma unroll 8
    for (int j = 0; j < H_; j++)
        acc = fmaf(h0p[j], wp[(size_t)j * 256], acc);
    ((float*)g_bias4)[idx] = acc;
}

// ---------------------------------------------------------------------------
// Kernel 4: fp16 2-term HMMA GEMM + fused LSTM epilogue.
//   CTA: 128m x 128n, 256 thr = 8 warps (4m x 2n), warp tile 32x64.
//   Terms: Ah*W + Al*W (W fragment loaded once, reused).
//   Chunks c 0..7 (kb = c>>1): even c = [Ah kb 16K | W kb 16K] (8 cp),
//   odd c = [Al kb 16K] (4 cp).  Ring of 3 slots x 32KB.
//   2 CTAs/SM; grid: x = nt 0..7 (32 h each), y = mt 0..1023.
// ---------------------------------------------------------------------------
#define CHUNK_BYTES 32768u
#define SMEM_SZ 98304
#define B3(x) ((x) % 3)

__global__ void __launch_bounds__(256, 2)
gemm_kernel(const float* __restrict__ c0, int l,
            float* __restrict__ hn, float* __restrict__ cn,
            float* __restrict__ x_out, int write_a)
{
    extern __shared__ __align__(1024) unsigned char smem[];
    const int tid = threadIdx.x;
    const int bx = blockIdx.x;
    const int mt = blockIdx.y;
    const int m0 = mt * 128;
    const uint32_t su = smem_u32(smem);
    const int lane = tid & 31, wid = tid >> 5;
    const int wm = wid >> 1, wn = wid & 1;

    const unsigned char* gWb = g_W + (size_t)(l * 8 + bx) * 65536;
    const unsigned char* gAb = g_A + (size_t)mt * 131072;

#define ISSUE_CHUNK(c, buf)                                                      \
    do {                                                                         \
        int kb_ = (c) >> 1;                                                      \
        uint32_t da = su + (buf) * CHUNK_BYTES + tid * 16;                       \
        if (((c) & 1) == 0) {                                                    \
            const unsigned char* sa = gAb + kb_ * 16384 + tid * 16;              \
            const unsigned char* sb = gWb + (size_t)kb_ * 16384 + tid * 16;      \
            CP16(da, sa); CP16(da + 4096, sa + 4096);                            \
            CP16(da + 8192, sa + 8192); CP16(da + 12288, sa + 12288);            \
            CP16(da + 16384, sb); CP16(da + 20480, sb + 4096);                   \
            CP16(da + 24576, sb + 8192); CP16(da + 28672, sb + 12288);           \
        } else {                                                                 \
            const unsigned char* sa = gAb + 65536 + kb_ * 16384 + tid * 16;      \
            CP16(da, sa); CP16(da + 4096, sa + 4096);                            \
            CP16(da + 8192, sa + 8192); CP16(da + 12288, sa + 12288);            \
        }                                                                        \
        CP_COMMIT();                                                             \
    } while (0)

    // prologue: prefill chunks 0, 1, 2
    ISSUE_CHUNK(0, 0);
    ISSUE_CHUNK(1, 1);
    ISSUE_CHUNK(2, 2);

    // per-lane ldmatrix offsets
    uint32_t aoff[2], aswz[2], boff[4], bswz[4];
    const uint32_t ua = (uint32_t)(lane >> 4);
    const uint32_t ub = (uint32_t)((lane >> 3) & 1);
#pragma unroll
    for (int tm = 0; tm < 2; tm++) {
        uint32_t row = (uint32_t)(wm * 32 + tm * 16 + (lane & 15));
        aoff[tm] = row * 128u;
        aswz[tm] = row & 7u;
    }
#pragma unroll
    for (int tn = 0; tn < 4; tn++) {
        uint32_t row = (uint32_t)(wn * 64 + tn * 16 + (lane & 7) + ((lane >> 4) << 3));
        boff[tn] = row * 128u + 16384u;           // W region inside even chunk
        bswz[tn] = row & 7u;
    }

    float acc[2][8][4];
#pragma unroll
    for (int i = 0; i < 2; i++)
#pragma unroll
        for (int j = 0; j < 8; j++)
#pragma unroll
            for (int q = 0; q < 4; q++) acc[i][j][q] = 0.0f;

    // mainloop: 4 kb-groups, each = even chunk (Ah|W) + odd chunk (Al)
#pragma unroll 1
    for (int g = 0; g < 4; g++) {
        if (g == 3) { CP_WAIT0(); } else { CP_WAIT1(); }
        __syncthreads();

        const int ce = 2 * g;
        const uint32_t be = su + (uint32_t)B3(ce) * CHUNK_BYTES;       // Ah | W
        const uint32_t bo = su + (uint32_t)B3(ce + 1) * CHUNK_BYTES;   // Al

#pragma unroll
        for (int ks = 0; ks < 4; ks++) {
            uint32_t ah[2][4], al[2][4], w[4][4];
            const uint32_t ka = (uint32_t)(ks * 2) + ua;
            const uint32_t kv = (uint32_t)(ks * 2) + ub;

            // term 1: Ah * W
#pragma unroll
            for (int tm = 0; tm < 2; tm++)
                LDSM4(ah[tm], be + aoff[tm] + ((ka ^ aswz[tm]) << 4));
#pragma unroll
            for (int tn = 0; tn < 4; tn++)
                LDSM4(w[tn], be + boff[tn] + ((kv ^ bswz[tn]) << 4));
#pragma unroll
            for (int tm = 0; tm < 2; tm++)
#pragma unroll
                for (int tn = 0; tn < 4; tn++) {
                    MMA(acc[tm][tn * 2 + 0], ah[tm], w[tn][0], w[tn][1]);
                    MMA(acc[tm][tn * 2 + 1], ah[tm], w[tn][2], w[tn][3]);
                }

            // term 2: Al * W (W still in regs)
#pragma unroll
            for (int tm = 0; tm < 2; tm++)
                LDSM4(al[tm], bo + aoff[tm] + ((ka ^ aswz[tm]) << 4));
#pragma unroll
            for (int tm = 0; tm < 2; tm++)
#pragma unroll
                for (int tn = 0; tn < 4; tn++) {
                    MMA(acc[tm][tn * 2 + 0], al[tm], w[tn][0], w[tn][1]);
                    MMA(acc[tm][tn * 2 + 1], al[tm], w[tn][2], w[tn][3]);
                }
        }
        __syncthreads();

        // refill freed buffers
        if (g == 0) { ISSUE_CHUNK(3, B3(3)); ISSUE_CHUNK(4, B3(4)); }
        else if (g == 1) { ISSUE_CHUNK(5, B3(5)); ISSUE_CHUNK(6, B3(6)); }
        else if (g == 2) { ISSUE_CHUNK(7, B3(7)); }
    }

    // stage accumulators to smem (128 rows x 128 cols, row pad 132 floats)
    {
        float* stage = (float*)smem;
        const int r0 = lane >> 2, cp2 = (lane & 3) * 2;
#pragma unroll
        for (int tm = 0; tm < 2; tm++) {
            int mr = wm * 32 + tm * 16 + r0;
#pragma unroll
            for (int j = 0; j < 8; j++) {
                int nc = wn * 64 + j * 8 + cp2;
                stage[(size_t)mr * 132 + nc]           = acc[tm][j][0];
                stage[(size_t)mr * 132 + nc + 1]       = acc[tm][j][1];
                stage[(size_t)(mr + 8) * 132 + nc]     = acc[tm][j][2];
                stage[(size_t)(mr + 8) * 132 + nc + 1] = acc[tm][j][3];
            }
        }
    }
    __syncthreads();

    // fused LSTM epilogue: 512 items = 128 rows x 4 (8 h each, 32 h total)
    {
        const float* stage = (const float*)smem;
#pragma unroll 1
        for (int u = 0; u < 2; u++) {
            int item = u * 256 + tid;
            int hu = item & 3, mloc = item >> 2;
            int m = m0 + mloc;
            int t = m >> 6, b = m & 63;
            int hbase = bx * 32 + hu * 8;

            const float4* bp = g_bias4 + (size_t)(l * B_ + b) * H_ + hbase;
            const float* c0p = c0 + ((size_t)l * B_ + b) * H_ + hbase;
            float hv[8], cc[8];
#pragma unroll
            for (int q = 0; q < 8; q++) {
                float4 pre = *(const float4*)&stage[(size_t)mloc * 132 + (hu * 8 + q) * 4];
                float4 bv = bp[q];
                float f  = sigmoidf_(pre.x + bv.x);
                float ii = sigmoidf_(pre.y + bv.y);
                float gt = tanhf_(pre.z + bv.z);
                float o  = sigmoidf_(pre.w + bv.w);
                cc[q] = fmaf(f, c0p[q], ii * gt);
                hv[q] = o * tanhf_(cc[q]);
            }
            size_t ob = ((size_t)t * (L_ * B_) + (size_t)l * B_ + b) * H_ + hbase;
            *(float4*)&hn[ob]     = make_float4(hv[0], hv[1], hv[2], hv[3]);
            *(float4*)&hn[ob + 4] = make_float4(hv[4], hv[5], hv[6], hv[7]);
            *(float4*)&cn[ob]     = make_float4(cc[0], cc[1], cc[2], cc[3]);
            *(float4*)&cn[ob + 4] = make_float4(cc[4], cc[5], cc[6], cc[7]);

            if (write_a) {
                // emit fp16 hi/lo A-image unit (8 h = one 16B unit) for layer 1
                uint32_t hi[4], lo[4];
#pragma unroll
                for (int p = 0; p < 4; p++) {
                    float h0f = fp16_val(hv[2 * p]);
                    float h1f = fp16_val(hv[2 * p + 1]);
                    hi[p] = pack_fp16x2(hv[2 * p], hv[2 * p + 1]);
                    lo[p] = pack_fp16x2(hv[2 * p] - h0f, hv[2 * p + 1] - h1f);
                }
                int k8 = hbase >> 3;              // unit index 0..31
                int kb_a = k8 >> 3, j_a = k8 & 7;
                size_t base = (size_t)mt * 131072 + (size_t)kb_a * 16384 +
                              (size_t)mloc * 128 +
                              (((unsigned)j_a ^ ((unsigned)mloc & 7)) << 4);
                *(uint4*)(g_A + base)         = make_uint4(hi[0], hi[1], hi[2], hi[3]);
                *(uint4*)(g_A + base + 65536) = make_uint4(lo[0], lo[1], lo[2], lo[3]);
            } else if (x_out) {
                float* xp = x_out + (size_t)m * H_ + hbase;
                *(float4*)xp       = make_float4(hv[0], hv[1], hv[2], hv[3]);
                *(float4*)(xp + 4) = make_float4(hv[4], hv[5], hv[6], hv[7]);
            }
        }
    }
#undef ISSUE_CHUNK
}

// ---------------------------------------------------------------------------
// Launch. Output layout: [ x (T*B*H) | h_n (T*L*B*H) | c_n (T*L*B*H) ]
// ---------------------------------------------------------------------------
extern "C" void kernel_launch(void* const* d_in, const int* in_sizes, int n_in,
                              void* d_out, int out_size)
{
    const float* inputs = (const float*)d_in[0];   // [T,B,D]
    const float* h0     = (const float*)d_in[1];   // [L,B,H]
    const float* c0     = (const float*)d_in[2];   // [L,B,H]
    const float* W      = (const float*)d_in[3];   // [L,4,D+H,H]
    const float* bb     = (const float*)d_in[4];   // [L,4,H]

    float* out   = (float*)d_out;
    float* x_out = out;
    float* hn    = out + (size_t)T_ * B_ * H_;
    float* cn    = hn + (size_t)T_ * L_ * B_ * H_;

    cudaFuncSetAttribute(gemm_kernel,
                         cudaFuncAttributeMaxDynamicSharedMemorySize, SMEM_SZ);

    wprep_kernel<<<256, 256>>>(W);        // exactly 65536 work items
    bias_kernel<<<512, 256>>>(h0, W, bb);
    aprep_kernel<<<16384, 256>>>(inputs, B_ * D_);

    dim3 grid(8, M_ / 128);
    // layer 0: epilogue also writes layer-1's fp16 A-image
    gemm_kernel<<<grid, 256, SMEM_SZ>>>(c0, 0, hn, cn, nullptr, 1);
    // layer 1: writes x
    gemm_kernel<<<grid, 256, SMEM_SZ>>>(c0, 1, hn, cn, x_out, 0);
}

// round 15
// speedup vs baseline: 4.0850x; 1.3805x over previous
#include <cuda_runtime.h>
#include <cuda_fp16.h>
#include <cstdint>

// Problem constants
#define T_ 2048
#define B_ 64
#define D_ 256
#define H_ 256
#define L_ 2
#define M_ (T_ * B_)       // 131072 GEMM rows per layer

// W image (single fp16): per (l, ntile 0..7): 4 kb-blocks,
// each block 128 n-rows x 64 k fp16 = 16KB, rows 128B, unit swz ((j^(row&7))<<4).
__device__ __align__(16) unsigned char g_W[(size_t)L_ * 8 * 4 * 16384]; // 1 MB
// A image (single fp16): per m-tile (128 rows): [kb0..3] 4 x 16KB = 64KB.
__device__ __align__(16) unsigned char g_A[(size_t)(M_ / 128) * 65536]; // 67 MB
__device__ __align__(16) float4 g_bias4[(size_t)L_ * B_ * H_];          // [l][b][h].(f,i,g,o)

// ---------------------------------------------------------------------------
// helpers
// ---------------------------------------------------------------------------
__device__ __forceinline__ uint32_t smem_u32(const void* p)
{
    uint32_t a;
    asm("{ .reg .u64 t; cvta.to.shared.u64 t, %1; cvt.u32.u64 %0, t; }" : "=r"(a) : "l"(p));
    return a;
}
__device__ __forceinline__ unsigned short fp16_bits(float v)
{
    __half h = __float2half_rn(v);
    return *reinterpret_cast<unsigned short*>(&h);
}
__device__ __forceinline__ uint32_t pack_fp16x2(float a, float b)
{
    __half2 h = __floats2half2_rn(a, b);
    return *reinterpret_cast<uint32_t*>(&h);
}
__device__ __forceinline__ float sigmoidf_(float x)
{
    return __fdividef(1.0f, 1.0f + __expf(-x));
}
__device__ __forceinline__ float tanhf_(float x)
{
    return 1.0f - __fdividef(2.0f, 1.0f + __expf(2.0f * x));
}

#define CP16(s, g) asm volatile("cp.async.cg.shared.global [%0], [%1], 16;" :: "r"(s), "l"(g))
#define CP_COMMIT() asm volatile("cp.async.commit_group;" ::: "memory")
#define CP_WAIT2() asm volatile("cp.async.wait_group 2;" ::: "memory")
#define CP_WAIT1() asm volatile("cp.async.wait_group 1;" ::: "memory")
#define CP_WAIT0() asm volatile("cp.async.wait_group 0;" ::: "memory")

#define LDSM4(r, addr) asm volatile( \
    "ldmatrix.sync.aligned.m8n8.x4.shared.b16 {%0,%1,%2,%3}, [%4];" \
    : "=r"((r)[0]), "=r"((r)[1]), "=r"((r)[2]), "=r"((r)[3]) : "r"(addr))

#define MMA(d, a, b0, b1) asm volatile( \
    "mma.sync.aligned.m16n8k16.row.col.f32.f16.f16.f32 " \
    "{%0,%1,%2,%3},{%4,%5,%6,%7},{%8,%9},{%0,%1,%2,%3};" \
    : "+f"((d)[0]), "+f"((d)[1]), "+f"((d)[2]), "+f"((d)[3]) \
    : "r"((a)[0]), "r"((a)[1]), "r"((a)[2]), "r"((a)[3]), "r"(b0), "r"(b1))

// ---------------------------------------------------------------------------
// Kernel 1: W -> single fp16 image, swizzled 16KB blocks (n = h*4+g interleave)
//   EXACTLY 65536 items (256 blocks): j:3 | nloc:7 | kb:2 | nt:3 | l:1
// ---------------------------------------------------------------------------
__global__ void __launch_bounds__(256) wprep_kernel(const float* __restrict__ W)
{
    int idx = blockIdx.x * 256 + threadIdx.x;      // 65536 total
    int j = idx & 7;
    int nloc = (idx >> 3) & 127;
    int kb = (idx >> 10) & 3;
    int nt = (idx >> 12) & 7;
    int l = (idx >> 15) & 1;

    int n = nt * 128 + nloc, g = n & 3, h = n >> 2;
    int k0 = kb * 64 + j * 8;
    const float* wp = W + ((size_t)(l * 4 + g) * 512 + k0) * 256 + h;

    unsigned short v[8];
#pragma unroll
    for (int i = 0; i < 8; i++)
        v[i] = fp16_bits(wp[(size_t)i * 256]);

    uint4 out;
    out.x = (uint32_t)v[0] | ((uint32_t)v[1] << 16);
    out.y = (uint32_t)v[2] | ((uint32_t)v[3] << 16);
    out.z = (uint32_t)v[4] | ((uint32_t)v[5] << 16);
    out.w = (uint32_t)v[6] | ((uint32_t)v[7] << 16);
    unsigned off = (unsigned)nloc * 128 + (((unsigned)j ^ ((unsigned)nloc & 7)) << 4);
    size_t blk = (size_t)(l * 8 + nt) * 4 + kb;
    *(uint4*)(g_W + blk * 16384 + off) = out;
}

// ---------------------------------------------------------------------------
// Kernel 2: A(fp32) -> single fp16 swizzled image g_A (layer 0 inputs only).
// ---------------------------------------------------------------------------
__global__ void __launch_bounds__(256) aprep_kernel(const float* __restrict__ A, int t_stride)
{
    int idx = blockIdx.x * 256 + threadIdx.x;      // 4,194,304
    int k8 = idx & 31;
    int m = idx >> 5;

    const float* gp = A + (size_t)(m >> 6) * t_stride + (size_t)(m & 63) * 256 + k8 * 8;
    float4 va = *(const float4*)gp;
    float4 vb = *(const float4*)(gp + 4);
    uint4 out;
    out.x = pack_fp16x2(va.x, va.y);
    out.y = pack_fp16x2(va.z, va.w);
    out.z = pack_fp16x2(vb.x, vb.y);
    out.w = pack_fp16x2(vb.z, vb.w);

    int mt = m >> 7, mloc = m & 127, kb = k8 >> 3, j = k8 & 7;
    size_t base = (size_t)mt * 65536 + (size_t)kb * 16384 + (size_t)mloc * 128 +
                  (((unsigned)j ^ ((unsigned)mloc & 7)) << 4);
    *(uint4*)(g_A + base) = out;
}

// ---------------------------------------------------------------------------
// Kernel 3: effective bias (exact fp32): b[l,g,h] + sum_j h0[l,b,j]*W[l,g,D+j,h]
// ---------------------------------------------------------------------------
__global__ void __launch_bounds__(256) bias_kernel(const float* __restrict__ h0,
                                                   const float* __restrict__ W,
                                                   const float* __restrict__ bb)
{
    int idx = blockIdx.x * 256 + threadIdx.x;      // 131072
    int g = idx & 3;
    int h = (idx >> 2) & 255;
    int b = (idx >> 10) & 63;
    int l = (idx >> 16) & 1;

    const float* h0p = h0 + (l * B_ + b) * H_;
    const float* wp  = W + ((size_t)(l * 4 + g) * 512 + 256) * 256 + h;
    float acc = bb[(l * 4 + g) * H_ + h];
#pragma unroll 8
    for (int j = 0; j < H_; j++)
        acc = fmaf(h0p[j], wp[(size_t)j * 256], acc);
    ((float*)g_bias4)[idx] = acc;
}

// ---------------------------------------------------------------------------
// Kernel 4: single-term fp16 HMMA GEMM + fused LSTM epilogue.
//   CTA: 128m x 128n, 256 thr = 8 warps (4m x 2n), warp tile 32x64.
//   4 chunks (kb 0..3) of [A 16KB | W 16KB] = 32KB, ring of 3, prefill 3.
//   2 CTAs/SM; grid: x = nt 0..7 (32 h each), y = mt 0..1023.
// ---------------------------------------------------------------------------
#define CHUNK_BYTES 32768u
#define SMEM_SZ 98304
#define B3(x) ((x) % 3)

__global__ void __launch_bounds__(256, 2)
gemm_kernel(const float* __restrict__ c0, int l,
            float* __restrict__ hn, float* __restrict__ cn,
            float* __restrict__ x_out, int write_a)
{
    extern __shared__ __align__(1024) unsigned char smem[];
    const int tid = threadIdx.x;
    const int bx = blockIdx.x;
    const int mt = blockIdx.y;
    const int m0 = mt * 128;
    const uint32_t su = smem_u32(smem);
    const int lane = tid & 31, wid = tid >> 5;
    const int wm = wid >> 1, wn = wid & 1;

    const unsigned char* gWb = g_W + (size_t)(l * 8 + bx) * 65536;
    const unsigned char* gAb = g_A + (size_t)mt * 65536;

#define ISSUE_CHUNK(kb, buf)                                                      \
    do {                                                                          \
        const unsigned char* sa = gAb + (kb) * 16384 + tid * 16;                  \
        const unsigned char* sb = gWb + (size_t)(kb) * 16384 + tid * 16;          \
        uint32_t da = su + (buf) * CHUNK_BYTES + tid * 16;                        \
        CP16(da, sa); CP16(da + 4096, sa + 4096);                                 \
        CP16(da + 8192, sa + 8192); CP16(da + 12288, sa + 12288);                 \
        CP16(da + 16384, sb); CP16(da + 20480, sb + 4096);                        \
        CP16(da + 24576, sb + 8192); CP16(da + 28672, sb + 12288);                \
        CP_COMMIT();                                                              \
    } while (0)

    // prologue: prefill chunks 0, 1, 2
    ISSUE_CHUNK(0, 0);
    ISSUE_CHUNK(1, 1);
    ISSUE_CHUNK(2, 2);

    // per-lane ldmatrix offsets
    uint32_t aoff[2], aswz[2], boff[4], bswz[4];
    const uint32_t ua = (uint32_t)(lane >> 4);
    const uint32_t ub = (uint32_t)((lane >> 3) & 1);
#pragma unroll
    for (int tm = 0; tm < 2; tm++) {
        uint32_t row = (uint32_t)(wm * 32 + tm * 16 + (lane & 15));
        aoff[tm] = row * 128u;
        aswz[tm] = row & 7u;
    }
#pragma unroll
    for (int tn = 0; tn < 4; tn++) {
        uint32_t row = (uint32_t)(wn * 64 + tn * 16 + (lane & 7) + ((lane >> 4) << 3));
        boff[tn] = row * 128u + 16384u;           // W region inside chunk
        bswz[tn] = row & 7u;
    }

    float acc[2][8][4];
#pragma unroll
    for (int i = 0; i < 2; i++)
#pragma unroll
        for (int j = 0; j < 8; j++)
#pragma unroll
            for (int q = 0; q < 4; q++) acc[i][j][q] = 0.0f;

    // mainloop: 4 kb-chunks (K = 256)
#pragma unroll 1
    for (int kb = 0; kb < 4; kb++) {
        if (kb == 0) { CP_WAIT2(); }
        else if (kb == 1) { CP_WAIT2(); }
        else if (kb == 2) { CP_WAIT1(); }
        else { CP_WAIT0(); }
        __syncthreads();

        const uint32_t bb = su + (uint32_t)B3(kb) * CHUNK_BYTES;

#pragma unroll
        for (int ks = 0; ks < 4; ks++) {
            uint32_t a[2][4], w[4][4];
            const uint32_t ka = (uint32_t)(ks * 2) + ua;
            const uint32_t kv = (uint32_t)(ks * 2) + ub;

#pragma unroll
            for (int tm = 0; tm < 2; tm++)
                LDSM4(a[tm], bb + aoff[tm] + ((ka ^ aswz[tm]) << 4));
#pragma unroll
            for (int tn = 0; tn < 4; tn++)
                LDSM4(w[tn], bb + boff[tn] + ((kv ^ bswz[tn]) << 4));
#pragma unroll
            for (int tm = 0; tm < 2; tm++)
#pragma unroll
                for (int tn = 0; tn < 4; tn++) {
                    MMA(acc[tm][tn * 2 + 0], a[tm], w[tn][0], w[tn][1]);
                    MMA(acc[tm][tn * 2 + 1], a[tm], w[tn][2], w[tn][3]);
                }
        }
        __syncthreads();

        if (kb == 0)
            ISSUE_CHUNK(3, 0);
    }

    // stage accumulators to smem (128 rows x 128 cols, row pad 132 floats)
    {
        float* stage = (float*)smem;
        const int r0 = lane >> 2, cp2 = (lane & 3) * 2;
#pragma unroll
        for (int tm = 0; tm < 2; tm++) {
            int mr = wm * 32 + tm * 16 + r0;
#pragma unroll
            for (int j = 0; j < 8; j++) {
                int nc = wn * 64 + j * 8 + cp2;
                stage[(size_t)mr * 132 + nc]           = acc[tm][j][0];
                stage[(size_t)mr * 132 + nc + 1]       = acc[tm][j][1];
                stage[(size_t)(mr + 8) * 132 + nc]     = acc[tm][j][2];
                stage[(size_t)(mr + 8) * 132 + nc + 1] = acc[tm][j][3];
            }
        }
    }
    __syncthreads();

    // fused LSTM epilogue: 512 items = 128 rows x 4 (8 h each, 32 h total)
    {
        const float* stage = (const float*)smem;
#pragma unroll 1
        for (int u = 0; u < 2; u++) {
            int item = u * 256 + tid;
            int hu = item & 3, mloc = item >> 2;
            int m = m0 + mloc;
            int t = m >> 6, b = m & 63;
            int hbase = bx * 32 + hu * 8;

            const float4* bp = g_bias4 + (size_t)(l * B_ + b) * H_ + hbase;
            const float* c0p = c0 + ((size_t)l * B_ + b) * H_ + hbase;
            float hv[8], cc[8];
#pragma unroll
            for (int q = 0; q < 8; q++) {
                float4 pre = *(const float4*)&stage[(size_t)mloc * 132 + (hu * 8 + q) * 4];
                float4 bv = bp[q];
                float f  = sigmoidf_(pre.x + bv.x);
                float ii = sigmoidf_(pre.y + bv.y);
                float gt = tanhf_(pre.z + bv.z);
                float o  = sigmoidf_(pre.w + bv.w);
                cc[q] = fmaf(f, c0p[q], ii * gt);
                hv[q] = o * tanhf_(cc[q]);
            }
            size_t ob = ((size_t)t * (L_ * B_) + (size_t)l * B_ + b) * H_ + hbase;
            *(float4*)&hn[ob]     = make_float4(hv[0], hv[1], hv[2], hv[3]);
            *(float4*)&hn[ob + 4] = make_float4(hv[4], hv[5], hv[6], hv[7]);
            *(float4*)&cn[ob]     = make_float4(cc[0], cc[1], cc[2], cc[3]);
            *(float4*)&cn[ob + 4] = make_float4(cc[4], cc[5], cc[6], cc[7]);

            if (write_a) {
                // emit fp16 A-image unit (8 h = one 16B unit) for layer 1
                uint4 out;
                out.x = pack_fp16x2(hv[0], hv[1]);
                out.y = pack_fp16x2(hv[2], hv[3]);
                out.z = pack_fp16x2(hv[4], hv[5]);
                out.w = pack_fp16x2(hv[6], hv[7]);
                int k8 = hbase >> 3;              // unit index 0..31
                int kb_a = k8 >> 3, j_a = k8 & 7;
                size_t base = (size_t)mt * 65536 + (size_t)kb_a * 16384 +
                              (size_t)mloc * 128 +
                              (((unsigned)j_a ^ ((unsigned)mloc & 7)) << 4);
                *(uint4*)(g_A + base) = out;
            } else if (x_out) {
                float* xp = x_out + (size_t)m * H_ + hbase;
                *(float4*)xp       = make_float4(hv[0], hv[1], hv[2], hv[3]);
                *(float4*)(xp + 4) = make_float4(hv[4], hv[5], hv[6], hv[7]);
            }
        }
    }
#undef ISSUE_CHUNK
}

// ---------------------------------------------------------------------------
// Launch. Output layout: [ x (T*B*H) | h_n (T*L*B*H) | c_n (T*L*B*H) ]
// ---------------------------------------------------------------------------
extern "C" void kernel_launch(void* const* d_in, const int* in_sizes, int n_in,
                              void* d_out, int out_size)
{
    const float* inputs = (const float*)d_in[0];   // [T,B,D]
    const float* h0     = (const float*)d_in[1];   // [L,B,H]
    const float* c0     = (const float*)d_in[2];   // [L,B,H]
    const float* W      = (const float*)d_in[3];   // [L,4,D+H,H]
    const float* bb     = (const float*)d_in[4];   // [L,4,H]

    float* out   = (float*)d_out;
    float* x_out = out;
    float* hn    = out + (size_t)T_ * B_ * H_;
    float* cn    = hn + (size_t)T_ * L_ * B_ * H_;

    cudaFuncSetAttribute(gemm_kernel,
                         cudaFuncAttributeMaxDynamicSharedMemorySize, SMEM_SZ);

    wprep_kernel<<<256, 256>>>(W);        // exactly 65536 work items
    bias_kernel<<<512, 256>>>(h0, W, bb);
    aprep_kernel<<<16384, 256>>>(inputs, B_ * D_);

    dim3 grid(8, M_ / 128);
    // layer 0: epilogue also writes layer-1's fp16 A-image
    gemm_kernel<<<grid, 256, SMEM_SZ>>>(c0, 0, hn, cn, nullptr, 1);
    // layer 1: writes x
    gemm_kernel<<<grid, 256, SMEM_SZ>>>(c0, 1, hn, cn, x_out, 0);
}